// round 3
// baseline (speedup 1.0000x reference)
#include <cuda_runtime.h>
#include <math.h>

#define B_    2
#define L_    2048
#define DIM_  2048
#define NH_   16
#define HD_   128
#define SCALE_ 0.08838834764831845f   // 1/sqrt(128)

// ---------------- scratch (no allocations allowed) ----------------
__device__ float g_q[(size_t)B_ * L_ * DIM_];
__device__ float g_k[(size_t)B_ * L_ * DIM_];
__device__ float g_v[(size_t)B_ * L_ * DIM_];
__device__ float g_o[(size_t)B_ * L_ * DIM_];

// ============================================================================
// GEMM + bias:  C[M, ldc slice] = A[M,K] @ W[K, ldw][:, col0:col0+N] + bias
// 128x128 block tile, BK=8, 256 threads, 8x8 micro-tile per thread.
// ============================================================================
__global__ __launch_bounds__(256) void gemm_bias_kernel(
    const float* __restrict__ A, const float* __restrict__ W,
    const float* __restrict__ bias, float* __restrict__ C,
    int M, int K, int ldw, int col0, int ldc)
{
    __shared__ float As[8][128];   // [k][m] transposed
    __shared__ float Bs[8][128];   // [k][n]

    const int tid = threadIdx.x;
    const int n0 = blockIdx.x * 128;
    const int m0 = blockIdx.y * 128;
    const int ty = tid >> 4;           // 0..15
    const int tx = tid & 15;           // 0..15

    // load mapping
    const int arow = tid >> 1;               // 0..127
    const int ac4  = (tid & 1) * 4;          // 0 or 4
    const int wrow = tid >> 5;               // 0..7
    const int wc4  = (tid & 31) * 4;         // 0..124

    float acc[8][8];
#pragma unroll
    for (int i = 0; i < 8; i++)
#pragma unroll
        for (int j = 0; j < 8; j++) acc[i][j] = 0.f;

    const float* Aptr = A + (size_t)(m0 + arow) * K + ac4;
    const float* Wptr = W + (size_t)wrow * ldw + col0 + n0 + wc4;

    for (int kt = 0; kt < K; kt += 8) {
        float4 a4 = *(const float4*)(Aptr + kt);
        float4 w4 = *(const float4*)(Wptr + (size_t)kt * ldw);
        __syncthreads();
        As[ac4 + 0][arow] = a4.x;
        As[ac4 + 1][arow] = a4.y;
        As[ac4 + 2][arow] = a4.z;
        As[ac4 + 3][arow] = a4.w;
        *(float4*)&Bs[wrow][wc4] = w4;
        __syncthreads();

#pragma unroll
        for (int kk = 0; kk < 8; kk++) {
            float av[8], bv[8];
            *(float4*)&av[0] = *(const float4*)&As[kk][ty * 8];
            *(float4*)&av[4] = *(const float4*)&As[kk][ty * 8 + 4];
            *(float4*)&bv[0] = *(const float4*)&Bs[kk][tx * 8];
            *(float4*)&bv[4] = *(const float4*)&Bs[kk][tx * 8 + 4];
#pragma unroll
            for (int i = 0; i < 8; i++)
#pragma unroll
                for (int j = 0; j < 8; j++)
                    acc[i][j] += av[i] * bv[j];
        }
    }

    // epilogue: bias + store
    float bv[8];
#pragma unroll
    for (int j = 0; j < 8; j++) bv[j] = bias[col0 + n0 + tx * 8 + j];

#pragma unroll
    for (int i = 0; i < 8; i++) {
        const int row = m0 + ty * 8 + i;
        float4 o0, o1;
        o0.x = acc[i][0] + bv[0]; o0.y = acc[i][1] + bv[1];
        o0.z = acc[i][2] + bv[2]; o0.w = acc[i][3] + bv[3];
        o1.x = acc[i][4] + bv[4]; o1.y = acc[i][5] + bv[5];
        o1.z = acc[i][6] + bv[6]; o1.w = acc[i][7] + bv[7];
        float* cp = C + (size_t)row * ldc + n0 + tx * 8;
        *(float4*)cp       = o0;
        *(float4*)(cp + 4) = o1;
    }
}

// ============================================================================
// Flash attention (fp32): one CTA = (batch, head, 64-query tile).
// 64x64 S tiles, online softmax, P staged through smem transposed.
// ============================================================================
#define BQ  64
#define BKV 64
#define PPAD 68   // pt row length in floats (16B-aligned, reduces conflicts)

struct AttnSmem {
    float qt[HD_][BQ];       // Q transposed  [kdim][qrow]   (pre-scaled by SCALE_)
    float kt[HD_][BKV];      // K transposed  [kdim][key]
    float vv[BKV][HD_];      // V natural     [key][kdim]
    float pt[BKV][PPAD];     // P transposed  [key][qrow]
};

__global__ __launch_bounds__(256) void attn_kernel(
    const float* __restrict__ Q, const float* __restrict__ Kp,
    const float* __restrict__ Vp, float* __restrict__ O)
{
    extern __shared__ char smem_raw[];
    AttnSmem& sm = *reinterpret_cast<AttnSmem*>(smem_raw);

    const int b  = blockIdx.y >> 4;
    const int h  = blockIdx.y & 15;
    const int q0 = blockIdx.x * BQ;
    const int tid = threadIdx.x;
    const int ty = tid >> 4;   // 0..15
    const int tx = tid & 15;   // 0..15

    const float* qbase = Q  + ((size_t)(b * L_ + q0)) * DIM_ + h * HD_;
    const float* kbase = Kp + ((size_t)(b * L_))      * DIM_ + h * HD_;
    const float* vbase = Vp + ((size_t)(b * L_))      * DIM_ + h * HD_;

    // load Q tile transposed, pre-scaled
    for (int i = tid; i < BQ * (HD_ / 4); i += 256) {
        int r  = i >> 5;            // 32 float4 per row
        int c4 = (i & 31) << 2;
        float4 t = *(const float4*)(qbase + (size_t)r * DIM_ + c4);
        sm.qt[c4 + 0][r] = t.x * SCALE_;
        sm.qt[c4 + 1][r] = t.y * SCALE_;
        sm.qt[c4 + 2][r] = t.z * SCALE_;
        sm.qt[c4 + 3][r] = t.w * SCALE_;
    }

    float acc[4][8];
#pragma unroll
    for (int i = 0; i < 4; i++)
#pragma unroll
        for (int c = 0; c < 8; c++) acc[i][c] = 0.f;
    float m_i[4] = {-1e30f, -1e30f, -1e30f, -1e30f};
    float l_i[4] = {0.f, 0.f, 0.f, 0.f};

    for (int t0 = 0; t0 < L_; t0 += BKV) {
        __syncthreads();   // previous iteration's pt/kt/vv consumers done
        // load K (transposed) and V tiles
        for (int i = tid; i < BKV * (HD_ / 4); i += 256) {
            int r  = i >> 5;
            int c4 = (i & 31) << 2;
            float4 k4 = *(const float4*)(kbase + (size_t)(t0 + r) * DIM_ + c4);
            sm.kt[c4 + 0][r] = k4.x;
            sm.kt[c4 + 1][r] = k4.y;
            sm.kt[c4 + 2][r] = k4.z;
            sm.kt[c4 + 3][r] = k4.w;
            float4 v4 = *(const float4*)(vbase + (size_t)(t0 + r) * DIM_ + c4);
            *(float4*)&sm.vv[r][c4] = v4;
        }
        __syncthreads();

        // S = (Q*scale) K^T   — thread owns rows 4ty..+3, cols 4tx..+3
        float s[4][4];
#pragma unroll
        for (int i = 0; i < 4; i++)
#pragma unroll
            for (int j = 0; j < 4; j++) s[i][j] = 0.f;

#pragma unroll 8
        for (int kd = 0; kd < HD_; kd++) {
            float aq[4], bk[4];
            *(float4*)&aq[0] = *(const float4*)&sm.qt[kd][ty * 4];
            *(float4*)&bk[0] = *(const float4*)&sm.kt[kd][tx * 4];
#pragma unroll
            for (int i = 0; i < 4; i++)
#pragma unroll
                for (int j = 0; j < 4; j++)
                    s[i][j] += aq[i] * bk[j];
        }

        // online softmax (row groups = 16 consecutive lanes, same ty)
#pragma unroll
        for (int i = 0; i < 4; i++) {
            float mt = fmaxf(fmaxf(s[i][0], s[i][1]), fmaxf(s[i][2], s[i][3]));
#pragma unroll
            for (int off = 8; off >= 1; off >>= 1)
                mt = fmaxf(mt, __shfl_xor_sync(0xffffffffu, mt, off));
            float mn = fmaxf(m_i[i], mt);
            float alpha = __expf(m_i[i] - mn);
            float rs = 0.f;
#pragma unroll
            for (int j = 0; j < 4; j++) {
                s[i][j] = __expf(s[i][j] - mn);
                rs += s[i][j];
            }
#pragma unroll
            for (int off = 8; off >= 1; off >>= 1)
                rs += __shfl_xor_sync(0xffffffffu, rs, off);
            l_i[i] = l_i[i] * alpha + rs;
            m_i[i] = mn;
#pragma unroll
            for (int c = 0; c < 8; c++) acc[i][c] *= alpha;
        }
        // write P transposed: pt[key][qrow]; float4 over the 4 q-rows
#pragma unroll
        for (int j = 0; j < 4; j++) {
            float4 pj;
            pj.x = s[0][j]; pj.y = s[1][j]; pj.z = s[2][j]; pj.w = s[3][j];
            *(float4*)&sm.pt[tx * 4 + j][ty * 4] = pj;
        }
        __syncthreads();

        // O += P @ V   — thread owns rows 4ty..+3, cols 8tx..+7
#pragma unroll 4
        for (int kk = 0; kk < BKV; kk++) {
            float pr[4], vr[8];
            *(float4*)&pr[0] = *(const float4*)&sm.pt[kk][ty * 4];
            *(float4*)&vr[0] = *(const float4*)&sm.vv[kk][tx * 8];
            *(float4*)&vr[4] = *(const float4*)&sm.vv[kk][tx * 8 + 4];
#pragma unroll
            for (int i = 0; i < 4; i++)
#pragma unroll
                for (int c = 0; c < 8; c++)
                    acc[i][c] += pr[i] * vr[c];
        }
    }

    // epilogue: normalize and store to [B, L, DIM] layout
#pragma unroll
    for (int i = 0; i < 4; i++) {
        float inv = 1.0f / l_i[i];
        const int row = q0 + ty * 4 + i;
        float* op = O + ((size_t)(b * L_ + row)) * DIM_ + h * HD_ + tx * 8;
        float4 o0, o1;
        o0.x = acc[i][0] * inv; o0.y = acc[i][1] * inv;
        o0.z = acc[i][2] * inv; o0.w = acc[i][3] * inv;
        o1.x = acc[i][4] * inv; o1.y = acc[i][5] * inv;
        o1.z = acc[i][6] * inv; o1.w = acc[i][7] * inv;
        *(float4*)op       = o0;
        *(float4*)(op + 4) = o1;
    }
}

// ============================================================================
// launch
// ============================================================================
extern "C" void kernel_launch(void* const* d_in, const int* in_sizes, int n_in,
                              void* d_out, int out_size)
{
    const float* x     = (const float*)d_in[0];
    const float* ctx   = (const float*)d_in[1];
    const float* Wqkv  = (const float*)d_in[2];
    const float* bqkv  = (const float*)d_in[3];
    const float* Wproj = (const float*)d_in[4];
    const float* bproj = (const float*)d_in[5];
    float* out = (float*)d_out;

    float *q, *k, *v, *o;
    cudaGetSymbolAddress((void**)&q, g_q);
    cudaGetSymbolAddress((void**)&k, g_k);
    cudaGetSymbolAddress((void**)&v, g_v);
    cudaGetSymbolAddress((void**)&o, g_o);

    const int smem_bytes = (int)sizeof(AttnSmem);   // 115712
    cudaFuncSetAttribute(attn_kernel,
                         cudaFuncAttributeMaxDynamicSharedMemorySize, smem_bytes);

    const int M = B_ * L_;
    dim3 tb(256);
    dim3 gp(DIM_ / 128, M / 128);

    // Q = x @ Wqkv[:, 0:2048] + b ; K,V from context
    gemm_bias_kernel<<<gp, tb>>>(x,   Wqkv, bqkv, q, M, DIM_, 3 * DIM_, 0,        DIM_);
    gemm_bias_kernel<<<gp, tb>>>(ctx, Wqkv, bqkv, k, M, DIM_, 3 * DIM_, DIM_,     DIM_);
    gemm_bias_kernel<<<gp, tb>>>(ctx, Wqkv, bqkv, v, M, DIM_, 3 * DIM_, 2 * DIM_, DIM_);

    attn_kernel<<<dim3(L_ / BQ, B_ * NH_), 256, smem_bytes>>>(q, k, v, o);

    gemm_bias_kernel<<<gp, tb>>>(o, Wproj, bproj, out, M, DIM_, DIM_, 0, DIM_);
}